// round 10
// baseline (speedup 1.0000x reference)
#include <cuda_runtime.h>
#include <math_constants.h>
#include <cstdint>

#define NROWS 2048
#define DIN   256
#define DPROJ 256   // Q[0:64) K[64:128) V[128:192) R[192:256)
#define DK    64
#define DR    64
#define DV    64

#define G_ROWS     8            // rows per CTA (one warp per row)
#define TILE_KEYS  32           // keys per smem K/V tile
#define HALF_KEYS  1024         // keys per CTA (row split in 2)
#define NT         (HALF_KEYS / TILE_KEYS)   // 32 tiles
#define NCTA_X     (NROWS / G_ROWS)          // 256
// dynamic smem: Ks[2][32][64] + Vs[2][32][64] + cm[16] + cl[16] + ca[8][2][64]
#define SMEM_FLOATS (2*TILE_KEYS*DK + 2*TILE_KEYS*DV + 16 + 16 + G_ROWS*2*DV)
#define SMEM_BYTES  (SMEM_FLOATS * 4)

// proj kernel smem: As[256][68] + Bs[256][68] (k-major, 64 rows used each)
#define PPAD 68
#define PROJ_SMEM_BYTES (2 * DIN * PPAD * 4)   // 139264

// Scratch
__device__ float g_proj[NROWS * DPROJ];          // projection (2 MB)
__device__ float g_ml[2][NROWS][2];              // per-half (M, L)
__device__ float g_pa[2][NROWS][DV];             // per-half unnormalized acc

__device__ __forceinline__ uint32_t smem_u32(const void* p) {
    return (uint32_t)__cvta_generic_to_shared(p);
}
__device__ __forceinline__ void cp16(uint32_t dst, const void* src) {
    asm volatile("cp.async.cg.shared.global [%0], [%1], 16;"
                 :: "r"(dst), "l"(src) : "memory");
}
__device__ __forceinline__ uint64_t mk_evict_first_policy() {
    uint64_t pol;
    asm("createpolicy.fractional.L2::evict_first.b64 %0, 1.0;" : "=l"(pol));
    return pol;
}
__device__ __forceinline__ float4 ldg_stream(const float* p, uint64_t pol) {
    float4 v;
    asm volatile("ld.global.nc.L2::cache_hint.v4.f32 {%0,%1,%2,%3}, [%4], %5;"
                 : "=f"(v.x), "=f"(v.y), "=f"(v.z), "=f"(v.w)
                 : "l"(p), "l"(pol));
    return v;
}

// ---------------------------------------------------------------------------
// Kernel 1: proj = H @ W^T.  BM=BN=64, 256 threads, 4x4 micro-tile.
// Full-K k-major staging of both tiles (one barrier), then 256 k-steps of
// 2 LDS.128 + 16 FMA. Grid (4,32)=128 CTAs, 1 CTA/SM, single wave.
// ---------------------------------------------------------------------------
__global__ __launch_bounds__(256, 1) void proj_gemm_kernel(
    const float* __restrict__ H, const float* __restrict__ W)
{
    extern __shared__ float psm[];
    float* As = psm;                   // [DIN][PPAD] rows 0..63 used
    float* Bs = psm + DIN * PPAD;      // [DIN][PPAD] rows 0..63 used

    const int tid = threadIdx.x;
    const int bm  = blockIdx.y * 64;
    const int bn  = blockIdx.x * 64;

    // ---- stage H tile (64 x 256) and W tile (64 x 256), k-major ----
    {
        const int row = tid >> 2;           // 0..63
        const int c   = (tid & 3) * 4;      // k sub-offset
#pragma unroll
        for (int kc = 0; kc < DIN; kc += 16) {
            float4 a4 = *(const float4*)&H[(size_t)(bm + row) * DIN + kc + c];
            As[(kc + c + 0) * PPAD + row] = a4.x;
            As[(kc + c + 1) * PPAD + row] = a4.y;
            As[(kc + c + 2) * PPAD + row] = a4.z;
            As[(kc + c + 3) * PPAD + row] = a4.w;
            float4 b4 = *(const float4*)&W[(size_t)(bn + row) * DIN + kc + c];
            Bs[(kc + c + 0) * PPAD + row] = b4.x;
            Bs[(kc + c + 1) * PPAD + row] = b4.y;
            Bs[(kc + c + 2) * PPAD + row] = b4.z;
            Bs[(kc + c + 3) * PPAD + row] = b4.w;
        }
    }
    __syncthreads();   // the only barrier

    const int tx = tid & 15;        // 4 output cols
    const int ty = tid >> 4;        // 4 output rows

    float acc[4][4];
#pragma unroll
    for (int a = 0; a < 4; a++)
#pragma unroll
        for (int b = 0; b < 4; b++) acc[a][b] = 0.f;

#pragma unroll 4
    for (int k = 0; k < DIN; k++) {
        const float4 af = *(const float4*)&As[k * PPAD + ty * 4];
        const float4 bf = *(const float4*)&Bs[k * PPAD + tx * 4];
        acc[0][0] = fmaf(af.x, bf.x, acc[0][0]);
        acc[0][1] = fmaf(af.x, bf.y, acc[0][1]);
        acc[0][2] = fmaf(af.x, bf.z, acc[0][2]);
        acc[0][3] = fmaf(af.x, bf.w, acc[0][3]);
        acc[1][0] = fmaf(af.y, bf.x, acc[1][0]);
        acc[1][1] = fmaf(af.y, bf.y, acc[1][1]);
        acc[1][2] = fmaf(af.y, bf.z, acc[1][2]);
        acc[1][3] = fmaf(af.y, bf.w, acc[1][3]);
        acc[2][0] = fmaf(af.z, bf.x, acc[2][0]);
        acc[2][1] = fmaf(af.z, bf.y, acc[2][1]);
        acc[2][2] = fmaf(af.z, bf.z, acc[2][2]);
        acc[2][3] = fmaf(af.z, bf.w, acc[2][3]);
        acc[3][0] = fmaf(af.w, bf.x, acc[3][0]);
        acc[3][1] = fmaf(af.w, bf.y, acc[3][1]);
        acc[3][2] = fmaf(af.w, bf.z, acc[3][2]);
        acc[3][3] = fmaf(af.w, bf.w, acc[3][3]);
    }

#pragma unroll
    for (int a = 0; a < 4; a++)
        *(float4*)&g_proj[(size_t)(bm + ty * 4 + a) * DPROJ + bn + tx * 4] =
            make_float4(acc[a][0], acc[a][1], acc[a][2], acc[a][3]);
}

// ---------------------------------------------------------------------------
// Kernel 2: partial fused attention.  (unchanged from R8)
// Grid (256, 2): blockIdx.x -> 8-row group, blockIdx.y = key half.
// 8 warps: warp w owns row w; 32-key K/V tiles double-buffered in smem,
// D streamed as 4 back-to-back LDG.128 per 8-key batch, evict-first.
// ---------------------------------------------------------------------------
__global__ void __launch_bounds__(256, 4) attn_partial_kernel(
    const float* __restrict__ D)
{
    extern __shared__ float smem[];
    float* Ks = smem;                       // [2][TILE_KEYS][DK]
    float* Vs = Ks + 2 * TILE_KEYS * DK;    // [2][TILE_KEYS][DV]
    float* cm = Vs + 2 * TILE_KEYS * DV;    // [G_ROWS][2]
    float* cl = cm + 16;                    // [G_ROWS][2]
    float* ca = cl + 16;                    // [G_ROWS][2][DV]

    const int tid  = threadIdx.x;
    const int warp = tid >> 5;           // = row within CTA
    const int lane = tid & 31;
    const int h    = lane >> 4;          // group in warp
    const int lx   = lane & 15;          // lane in group -> dims 4*lx..+4
    const int q    = blockIdx.y;         // key half
    const int i    = blockIdx.x * G_ROWS + warp;
    const int jq   = q * HALF_KEYS;

    const uint64_t pol = mk_evict_first_policy();

    const float scale = 0.08838834764831845f;  // 1/sqrt(128)
    float4 q4 = *(const float4*)&g_proj[(size_t)i * DPROJ + 4 * lx];
    float4 r4 = *(const float4*)&g_proj[(size_t)i * DPROJ + 192 + 4 * lx];
    q4.x *= scale; q4.y *= scale; q4.z *= scale; q4.w *= scale;
    r4.x *= scale; r4.y *= scale; r4.z *= scale; r4.w *= scale;

    const float* Drow = D + (size_t)i * NROWS * DR;

    // ---- prefetch tile 0 (K+V: 32 keys x 256B each = 16 KB) ----
    {
#pragma unroll
        for (int r = 0; r < 2; r++) {
            const int c   = tid + r * 256;      // 0..511
            const int key = c >> 4;
            const int off = c & 15;             // 16B units
            const float* src = &g_proj[(size_t)(jq + key) * DPROJ + off * 4];
            cp16(smem_u32(&Ks[key * DK + off * 4]), src + DK);
            cp16(smem_u32(&Vs[key * DV + off * 4]), src + 2 * DK);
        }
        asm volatile("cp.async.commit_group;" ::: "memory");
    }

    float  m = -CUDART_INF_F;
    float  l = 0.f;
    float4 acc = make_float4(0.f, 0.f, 0.f, 0.f);

#pragma unroll 1
    for (int t = 0; t < NT; t++) {
        const int st = t & 1;
        if (t + 1 < NT) {
            const int jt = jq + (t + 1) * TILE_KEYS;
            const int sn = (t + 1) & 1;
#pragma unroll
            for (int r = 0; r < 2; r++) {
                const int c   = tid + r * 256;
                const int key = c >> 4;
                const int off = c & 15;
                const float* src = &g_proj[(size_t)(jt + key) * DPROJ + off * 4];
                cp16(smem_u32(&Ks[sn * TILE_KEYS * DK + key * DK + off * 4]), src + DK);
                cp16(smem_u32(&Vs[sn * TILE_KEYS * DV + key * DV + off * 4]), src + 2 * DK);
            }
            asm volatile("cp.async.commit_group;" ::: "memory");
            asm volatile("cp.async.wait_group 1;" ::: "memory");
        } else {
            asm volatile("cp.async.wait_group 0;" ::: "memory");
        }
        __syncthreads();

        const float* Kt = Ks + st * TILE_KEYS * DK;
        const float* Vt = Vs + st * TILE_KEYS * DV;
        const int jt0 = jq + t * TILE_KEYS;

#pragma unroll
        for (int s = 0; s < 4; s++) {
            // ---- 8 keys per batch: 4 back-to-back 2KB-contiguous D loads ----
            float4 d4[4];
            float  sc[4];
#pragma unroll
            for (int u = 0; u < 4; u++) {
                const int kk = s * 8 + 2 * u + h;
                d4[u] = ldg_stream(&Drow[(size_t)(jt0 + kk) * DR + 4 * lx], pol);
            }
#pragma unroll
            for (int u = 0; u < 4; u++) {
                const int kk = s * 8 + 2 * u + h;
                const float4 k4 = *(const float4*)&Kt[kk * DK + 4 * lx];
                float t0 = d4[u].x * r4.x;
                t0 = fmaf(d4[u].y, r4.y, t0);
                t0 = fmaf(d4[u].z, r4.z, t0);
                t0 = fmaf(d4[u].w, r4.w, t0);
                t0 = fmaf(k4.x, q4.x, t0);
                t0 = fmaf(k4.y, q4.y, t0);
                t0 = fmaf(k4.z, q4.z, t0);
                t0 = fmaf(k4.w, q4.w, t0);
                sc[u] = t0;
            }
#pragma unroll
            for (int o = 1; o < 16; o <<= 1) {
#pragma unroll
                for (int u = 0; u < 4; u++)
                    sc[u] += __shfl_xor_sync(0xffffffffu, sc[u], o);
            }
            const float mnew = fmaxf(fmaxf(fmaxf(sc[0], sc[1]), fmaxf(sc[2], sc[3])), m);
            const float c = __expf(m - mnew);
            float w[4];
#pragma unroll
            for (int u = 0; u < 4; u++) w[u] = __expf(sc[u] - mnew);
            l = fmaf(l, c, (w[0] + w[1]) + (w[2] + w[3]));
            float ax = acc.x * c, ay = acc.y * c, az = acc.z * c, aw = acc.w * c;
#pragma unroll
            for (int u = 0; u < 4; u++) {
                const int kk = s * 8 + 2 * u + h;
                const float4 v4 = *(const float4*)&Vt[kk * DV + 4 * lx];
                ax = fmaf(w[u], v4.x, ax);
                ay = fmaf(w[u], v4.y, ay);
                az = fmaf(w[u], v4.z, az);
                aw = fmaf(w[u], v4.w, aw);
            }
            acc.x = ax; acc.y = ay; acc.z = az; acc.w = aw;
            m = mnew;
        }
        __syncthreads();   // tile consumed
    }

    // ---- combine the 2 group-partials per row ----
    if (lx == 0) { cm[warp * 2 + h] = m; cl[warp * 2 + h] = l; }
    *(float4*)&ca[(warp * 2 + h) * DV + 4 * lx] = acc;
    __syncthreads();

    {
        const int row = tid >> 5;           // 0..7
        const int dd  = (tid & 31) * 2;     // 2 dims per thread
        const int ig  = blockIdx.x * G_ROWS + row;
        const float m0 = cm[row * 2 + 0], m1 = cm[row * 2 + 1];
        const float M  = fmaxf(m0, m1);
        const float e0 = __expf(m0 - M);
        const float e1 = __expf(m1 - M);
        const float L  = e0 * cl[row * 2 + 0] + e1 * cl[row * 2 + 1];
        const float o0 = e0 * ca[(row * 2 + 0) * DV + dd + 0]
                       + e1 * ca[(row * 2 + 1) * DV + dd + 0];
        const float o1 = e0 * ca[(row * 2 + 0) * DV + dd + 1]
                       + e1 * ca[(row * 2 + 1) * DV + dd + 1];
        g_pa[q][ig][dd + 0] = o0;
        g_pa[q][ig][dd + 1] = o1;
        if (dd == 0) { g_ml[q][ig][0] = M; g_ml[q][ig][1] = L; }
    }
}

// ---------------------------------------------------------------------------
// Kernel 3: combine the two key-half partials per row.
// ---------------------------------------------------------------------------
__global__ __launch_bounds__(256) void combine_kernel(float* __restrict__ out)
{
    const int idx = blockIdx.x * 256 + threadIdx.x;   // 0 .. 2048*64-1
    const int i = idx >> 6;
    const int d = idx & 63;
    const float m0 = g_ml[0][i][0], l0 = g_ml[0][i][1];
    const float m1 = g_ml[1][i][0], l1 = g_ml[1][i][1];
    const float M  = fmaxf(m0, m1);
    const float e0 = __expf(m0 - M);
    const float e1 = __expf(m1 - M);
    const float L  = e0 * l0 + e1 * l1;
    out[idx] = (e0 * g_pa[0][i][d] + e1 * g_pa[1][i][d]) / L;
}

// ---------------------------------------------------------------------------
extern "C" void kernel_launch(void* const* d_in, const int* in_sizes, int n_in,
                              void* d_out, int out_size)
{
    const float* H = (const float*)d_in[0];   // (2048, 256)
    const float* D = (const float*)d_in[1];   // (2048, 2048, 64)
    const float* W = (const float*)d_in[2];   // (256, 256)
    float* out = (float*)d_out;               // (2048, 64)

    static bool attr_set = false;
    if (!attr_set) {
        cudaFuncSetAttribute(attn_partial_kernel,
                             cudaFuncAttributeMaxDynamicSharedMemorySize, SMEM_BYTES);
        cudaFuncSetAttribute(proj_gemm_kernel,
                             cudaFuncAttributeMaxDynamicSharedMemorySize, PROJ_SMEM_BYTES);
        attr_set = true;
    }

    dim3 g1(DPROJ / 64, NROWS / 64);          // (4, 32) = 128 blocks
    proj_gemm_kernel<<<g1, 256, PROJ_SMEM_BYTES>>>(H, W);
    attn_partial_kernel<<<dim3(NCTA_X, 2), 256, SMEM_BYTES>>>(D);
    combine_kernel<<<(NROWS * DV) / 256, 256>>>(out);
}